// round 1
// baseline (speedup 1.0000x reference)
#include <cuda_runtime.h>
#include <math.h>

// Problem constants (shapes are fixed by the reference)
#define C_DIM 1536
#define L_Q   2400
#define L_KV  512
#define NH    12
#define HD    128
#define FF_DIM 8960
#define EPS   1e-6f

// ---------------- device scratch (allocation-free rule: __device__ globals) ----
__device__ float g_em[6 * C_DIM];
__device__ float g_h [L_Q * C_DIM];
__device__ float g_q [L_Q * C_DIM];
__device__ float g_k [L_Q * C_DIM];
__device__ float g_v [L_Q * C_DIM];
__device__ float g_y [L_Q * C_DIM];
__device__ float g_t [L_Q * C_DIM];
__device__ float g_s [69120000];            // 12 * 2400 * 2400 scores
__device__ float g_ff[L_Q * FF_DIM];        // 2400 * 8960

// ---------------- helpers ----------------------------------------------------
__device__ __forceinline__ float block_reduce(float v, float* sh, bool is_max) {
    __syncthreads();  // protect sh reuse across calls
    int lane = threadIdx.x & 31, warp = threadIdx.x >> 5;
    #pragma unroll
    for (int o = 16; o > 0; o >>= 1) {
        float other = __shfl_down_sync(0xffffffffu, v, o);
        v = is_max ? fmaxf(v, other) : v + other;
    }
    if (lane == 0) sh[warp] = v;
    __syncthreads();
    int nw = blockDim.x >> 5;
    if (warp == 0) {
        v = (lane < nw) ? sh[lane] : (is_max ? -INFINITY : 0.f);
        #pragma unroll
        for (int o = 16; o > 0; o >>= 1) {
            float other = __shfl_down_sync(0xffffffffu, v, o);
            v = is_max ? fmaxf(v, other) : v + other;
        }
        if (lane == 0) sh[0] = v;
    }
    __syncthreads();
    return sh[0];
}

__device__ __forceinline__ float gelu_tanh(float v) {
    float v3 = v * v * v;
    return 0.5f * v * (1.f + tanhf(0.7978845608028654f * (v + 0.044715f * v3)));
}

// ---------------- small elementwise kernels ----------------------------------
__global__ void em_kernel(const float* __restrict__ e, const float* __restrict__ mod,
                          float* __restrict__ em) {
    int i = blockIdx.x * blockDim.x + threadIdx.x;
    if (i < 6 * C_DIM) em[i] = e[i] + mod[i];
}

// out[row] = e0 + LN(x[row]) * (1 + e1)
__global__ void ln_mod_kernel(const float* __restrict__ x, const float* __restrict__ e0,
                              const float* __restrict__ e1, float* __restrict__ out) {
    __shared__ float sh[32];
    long long row = blockIdx.x;
    const float* xr = x + row * C_DIM;
    float s = 0.f, s2 = 0.f;
    for (int c = threadIdx.x; c < C_DIM; c += blockDim.x) {
        float v = xr[c];
        s += v; s2 += v * v;
    }
    float S  = block_reduce(s,  sh, false);
    float S2 = block_reduce(s2, sh, false);
    float m   = S  * (1.f / C_DIM);
    float var = S2 * (1.f / C_DIM) - m * m;
    float inv = rsqrtf(var + EPS);
    float* orow = out + row * C_DIM;
    for (int c = threadIdx.x; c < C_DIM; c += blockDim.x)
        orow[c] = e0[c] + (xr[c] - m) * inv * (1.f + e1[c]);
}

// x[row] *= rsqrt(mean(x^2)+eps) * w   (in-place, row length C_DIM)
__global__ void rms_kernel(float* __restrict__ x, const float* __restrict__ w) {
    __shared__ float sh[32];
    long long row = blockIdx.x;
    float* xr = x + row * C_DIM;
    float s2 = 0.f;
    for (int c = threadIdx.x; c < C_DIM; c += blockDim.x) {
        float v = xr[c];
        s2 += v * v;
    }
    float S2 = block_reduce(s2, sh, false);
    float inv = rsqrtf(S2 * (1.f / C_DIM) + EPS);
    for (int c = threadIdx.x; c < C_DIM; c += blockDim.x)
        xr[c] = xr[c] * inv * w[c];
}

// RoPE, in place on [L_Q, NH*HD]; pair j of head n at col n*128 + 2j
__global__ void rope_kernel(float* __restrict__ x, const float* __restrict__ freqs) {
    long long idx = (long long)blockIdx.x * blockDim.x + threadIdx.x;
    if (idx >= (long long)L_Q * NH * 64) return;
    int j = (int)(idx & 63);
    int n = (int)((idx >> 6) % NH);
    int l = (int)(idx / (64 * NH));
    int f  = l / 1200;
    int rm = l % 1200;
    int hh = rm / 40;
    int ww = rm % 40;
    int pos = (j < 22) ? f : ((j < 43) ? hh : ww);
    float cs = freqs[(pos * 64 + j) * 2 + 0];
    float sn = freqs[(pos * 64 + j) * 2 + 1];
    float* p = x + (long long)l * C_DIM + n * HD + 2 * j;
    float a = p[0], b = p[1];
    p[0] = a * cs - b * sn;
    p[1] = a * sn + b * cs;
}

__global__ void softmax_kernel(float* __restrict__ s, int lk) {
    __shared__ float sh[32];
    long long row = blockIdx.x;
    float* p = s + row * (long long)lk;
    float mx = -INFINITY;
    for (int i = threadIdx.x; i < lk; i += blockDim.x) mx = fmaxf(mx, p[i]);
    mx = block_reduce(mx, sh, true);
    float sum = 0.f;
    for (int i = threadIdx.x; i < lk; i += blockDim.x) {
        float e = __expf(p[i] - mx);
        p[i] = e; sum += e;
    }
    sum = block_reduce(sum, sh, false);
    float inv = 1.f / sum;
    for (int i = threadIdx.x; i < lk; i += blockDim.x) p[i] *= inv;
}

// out = xin + t * ecol[col]
__global__ void residual_mul_kernel(const float* __restrict__ xin, const float* __restrict__ t,
                                    const float* __restrict__ ecol, float* __restrict__ out) {
    long long i = (long long)blockIdx.x * blockDim.x + threadIdx.x;
    if (i < (long long)L_Q * C_DIM) out[i] = xin[i] + t[i] * ecol[i % C_DIM];
}

__global__ void add_inplace_kernel(float* __restrict__ x, const float* __restrict__ t) {
    long long i = (long long)blockIdx.x * blockDim.x + threadIdx.x;
    if (i < (long long)L_Q * C_DIM) x[i] += t[i];
}

__global__ void addmul_inplace_kernel(float* __restrict__ x, const float* __restrict__ t,
                                      const float* __restrict__ ecol) {
    long long i = (long long)blockIdx.x * blockDim.x + threadIdx.x;
    if (i < (long long)L_Q * C_DIM) x[i] += t[i] * ecol[i % C_DIM];
}

// ---------------- generic tiled fp32 GEMM ------------------------------------
// C = act( scale * A@B(^T) + bias ), per-z pointer strides for per-head batching.
#define BM 64
#define BN 64
#define BK 16

__global__ void __launch_bounds__(256)
gemm_kernel(const float* __restrict__ A, int lda, long long sAz,
            const float* __restrict__ B, int ldb, long long sBz,
            float* __restrict__ C, int ldc, long long sCz,
            int M, int N, int K,
            const float* __restrict__ bias, float scale, int act, int transB) {
    __shared__ float As[BK][BM + 4];
    __shared__ float Bs[BK][BN + 4];

    A += (long long)blockIdx.z * sAz;
    B += (long long)blockIdx.z * sBz;
    C += (long long)blockIdx.z * sCz;

    int bm = blockIdx.y * BM;
    int bn = blockIdx.x * BN;
    int tid = threadIdx.x;
    int ty = tid >> 4;   // 0..15
    int tx = tid & 15;   // 0..15

    float acc[4][4] = {};

    for (int k0 = 0; k0 < K; k0 += BK) {
        // load A tile: As[k][m] = A[bm+m][k0+k]
        #pragma unroll
        for (int i = 0; i < 4; i++) {
            int idx = tid + i * 256;        // 0..1023
            int m  = idx >> 4;
            int kk = idx & 15;
            int gm = bm + m;
            As[kk][m] = (gm < M) ? A[(long long)gm * lda + k0 + kk] : 0.f;
        }
        // load B tile
        if (!transB) {
            #pragma unroll
            for (int i = 0; i < 4; i++) {
                int idx = tid + i * 256;
                int kk = idx >> 6;
                int n  = idx & 63;
                int gn = bn + n;
                Bs[kk][n] = (gn < N) ? B[(long long)(k0 + kk) * ldb + gn] : 0.f;
            }
        } else {
            #pragma unroll
            for (int i = 0; i < 4; i++) {
                int idx = tid + i * 256;
                int n  = idx >> 4;
                int kk = idx & 15;
                int gn = bn + n;
                Bs[kk][n] = (gn < N) ? B[(long long)gn * ldb + k0 + kk] : 0.f;
            }
        }
        __syncthreads();

        #pragma unroll
        for (int kk = 0; kk < BK; kk++) {
            float4 a4 = *reinterpret_cast<const float4*>(&As[kk][ty * 4]);
            float4 b4 = *reinterpret_cast<const float4*>(&Bs[kk][tx * 4]);
            float a[4] = {a4.x, a4.y, a4.z, a4.w};
            float b[4] = {b4.x, b4.y, b4.z, b4.w};
            #pragma unroll
            for (int i = 0; i < 4; i++)
                #pragma unroll
                for (int j = 0; j < 4; j++)
                    acc[i][j] += a[i] * b[j];
        }
        __syncthreads();
    }

    #pragma unroll
    for (int i = 0; i < 4; i++) {
        int gm = bm + ty * 4 + i;
        if (gm >= M) continue;
        #pragma unroll
        for (int j = 0; j < 4; j++) {
            int gn = bn + tx * 4 + j;
            if (gn >= N) continue;
            float v = acc[i][j] * scale;
            if (bias) v += bias[gn];
            if (act == 1) v = gelu_tanh(v);
            C[(long long)gm * ldc + gn] = v;
        }
    }
}

// ---------------- host side ---------------------------------------------------
static void gemm(const float* A, int lda, long long sAz,
                 const float* B, int ldb, long long sBz,
                 float* C, int ldc, long long sCz,
                 int M, int N, int K, int Z,
                 const float* bias, float scale, int act, int transB) {
    dim3 grid((N + BN - 1) / BN, (M + BM - 1) / BM, Z);
    gemm_kernel<<<grid, 256>>>(A, lda, sAz, B, ldb, sBz, C, ldc, sCz,
                               M, N, K, bias, scale, act, transB);
}

extern "C" void kernel_launch(void* const* d_in, const int* in_sizes, int n_in,
                              void* d_out, int out_size) {
    const float* x        = (const float*)d_in[0];
    const float* e        = (const float*)d_in[1];
    const float* context  = (const float*)d_in[2];
    const float* freqs    = (const float*)d_in[3];
    // d_in[4] seq_lens, d_in[5] context_lens, d_in[6] grid_sizes: constant, unused
    const float* modulation = (const float*)d_in[7];
    const float* sa_q_w = (const float*)d_in[8];
    const float* sa_q_b = (const float*)d_in[9];
    const float* sa_k_w = (const float*)d_in[10];
    const float* sa_k_b = (const float*)d_in[11];
    const float* sa_v_w = (const float*)d_in[12];
    const float* sa_v_b = (const float*)d_in[13];
    const float* sa_o_w = (const float*)d_in[14];
    const float* sa_o_b = (const float*)d_in[15];
    const float* sa_nq_w = (const float*)d_in[16];
    const float* sa_nk_w = (const float*)d_in[17];
    const float* ca_q_w = (const float*)d_in[18];
    const float* ca_q_b = (const float*)d_in[19];
    const float* ca_k_w = (const float*)d_in[20];
    const float* ca_k_b = (const float*)d_in[21];
    const float* ca_v_w = (const float*)d_in[22];
    const float* ca_v_b = (const float*)d_in[23];
    const float* ca_o_w = (const float*)d_in[24];
    const float* ca_o_b = (const float*)d_in[25];
    const float* ca_nq_w = (const float*)d_in[26];
    const float* ca_nk_w = (const float*)d_in[27];
    const float* ffn_w1 = (const float*)d_in[28];
    const float* ffn_b1 = (const float*)d_in[29];
    const float* ffn_w2 = (const float*)d_in[30];
    const float* ffn_b2 = (const float*)d_in[31];
    float* out = (float*)d_out;

    float *em, *h, *q, *k, *v, *y, *t, *s, *ff;
    cudaGetSymbolAddress((void**)&em, g_em);
    cudaGetSymbolAddress((void**)&h,  g_h);
    cudaGetSymbolAddress((void**)&q,  g_q);
    cudaGetSymbolAddress((void**)&k,  g_k);
    cudaGetSymbolAddress((void**)&v,  g_v);
    cudaGetSymbolAddress((void**)&y,  g_y);
    cudaGetSymbolAddress((void**)&t,  g_t);
    cudaGetSymbolAddress((void**)&s,  g_s);
    cudaGetSymbolAddress((void**)&ff, g_ff);

    const float ascale = 0.08838834764831845f;  // 1/sqrt(128)
    const long long LC = (long long)L_Q * C_DIM;
    int eltBlocks = (int)((LC + 255) / 256);
    int ropeBlocks = (int)(((long long)L_Q * NH * 64 + 255) / 256);

    // modulation vectors
    em_kernel<<<(6 * C_DIM + 255) / 256, 256>>>(e, modulation, em);

    // ---- self attention ----
    ln_mod_kernel<<<L_Q, 256>>>(x, em + 0 * C_DIM, em + 1 * C_DIM, h);
    gemm(h, C_DIM, 0, sa_q_w, C_DIM, 0, q, C_DIM, 0, L_Q, C_DIM, C_DIM, 1, sa_q_b, 1.f, 0, 0);
    gemm(h, C_DIM, 0, sa_k_w, C_DIM, 0, k, C_DIM, 0, L_Q, C_DIM, C_DIM, 1, sa_k_b, 1.f, 0, 0);
    gemm(h, C_DIM, 0, sa_v_w, C_DIM, 0, v, C_DIM, 0, L_Q, C_DIM, C_DIM, 1, sa_v_b, 1.f, 0, 0);
    rms_kernel<<<L_Q, 256>>>(q, sa_nq_w);
    rms_kernel<<<L_Q, 256>>>(k, sa_nk_w);
    rope_kernel<<<ropeBlocks, 256>>>(q, freqs);
    rope_kernel<<<ropeBlocks, 256>>>(k, freqs);
    // scores = scale * Q @ K^T per head
    gemm(q, C_DIM, HD, k, C_DIM, HD, s, L_Q, (long long)L_Q * L_Q,
         L_Q, L_Q, HD, NH, nullptr, ascale, 0, 1);
    softmax_kernel<<<NH * L_Q, 256>>>(s, L_Q);
    // y = P @ V per head, written straight into [L, C] layout
    gemm(s, L_Q, (long long)L_Q * L_Q, v, C_DIM, HD, y, C_DIM, HD,
         L_Q, HD, L_Q, NH, nullptr, 1.f, 0, 0);
    gemm(y, C_DIM, 0, sa_o_w, C_DIM, 0, t, C_DIM, 0, L_Q, C_DIM, C_DIM, 1, sa_o_b, 1.f, 0, 0);
    residual_mul_kernel<<<eltBlocks, 256>>>(x, t, em + 2 * C_DIM, out);

    // ---- cross attention ----
    gemm(out, C_DIM, 0, ca_q_w, C_DIM, 0, q, C_DIM, 0, L_Q, C_DIM, C_DIM, 1, ca_q_b, 1.f, 0, 0);
    rms_kernel<<<L_Q, 256>>>(q, ca_nq_w);
    gemm(context, C_DIM, 0, ca_k_w, C_DIM, 0, k, C_DIM, 0, L_KV, C_DIM, C_DIM, 1, ca_k_b, 1.f, 0, 0);
    rms_kernel<<<L_KV, 256>>>(k, ca_nk_w);
    gemm(context, C_DIM, 0, ca_v_w, C_DIM, 0, v, C_DIM, 0, L_KV, C_DIM, C_DIM, 1, ca_v_b, 1.f, 0, 0);
    gemm(q, C_DIM, HD, k, C_DIM, HD, s, L_KV, (long long)L_Q * L_KV,
         L_Q, L_KV, HD, NH, nullptr, ascale, 0, 1);
    softmax_kernel<<<NH * L_Q, 256>>>(s, L_KV);
    gemm(s, L_KV, (long long)L_Q * L_KV, v, C_DIM, HD, y, C_DIM, HD,
         L_Q, HD, L_KV, NH, nullptr, 1.f, 0, 0);
    gemm(y, C_DIM, 0, ca_o_w, C_DIM, 0, t, C_DIM, 0, L_Q, C_DIM, C_DIM, 1, ca_o_b, 1.f, 0, 0);
    add_inplace_kernel<<<eltBlocks, 256>>>(out, t);

    // ---- FFN ----
    ln_mod_kernel<<<L_Q, 256>>>(out, em + 3 * C_DIM, em + 4 * C_DIM, h);
    gemm(h, C_DIM, 0, ffn_w1, FF_DIM, 0, ff, FF_DIM, 0,
         L_Q, FF_DIM, C_DIM, 1, ffn_b1, 1.f, 1, 0);          // + GELU(tanh)
    gemm(ff, FF_DIM, 0, ffn_w2, C_DIM, 0, t, C_DIM, 0,
         L_Q, C_DIM, FF_DIM, 1, ffn_b2, 1.f, 0, 0);
    addmul_inplace_kernel<<<eltBlocks, 256>>>(out, t, em + 5 * C_DIM);
}

// round 4
// speedup vs baseline: 2.4486x; 2.4486x over previous
#include <cuda_runtime.h>
#include <cuda_bf16.h>
#include <stdint.h>
#include <math.h>

// Problem constants
#define C_DIM 1536
#define L_Q   2400
#define L_KV  512
#define NH    12
#define HD    128
#define FF_DIM 8960
#define EPS   1e-6f

// ---------------- device scratch ----------------
__device__ float g_em[6 * C_DIM];
__device__ float g_h [L_Q * C_DIM];
__device__ float g_q [L_Q * C_DIM];
__device__ float g_k [L_Q * C_DIM];
__device__ float g_v [L_Q * C_DIM];
__device__ float g_y [L_Q * C_DIM];
__device__ float g_t [L_Q * C_DIM];
__device__ float g_s [69120000];            // 12 * 2400 * 2400
__device__ float g_ff[L_Q * FF_DIM];

// ---------------- reductions / elementwise ----------------
__device__ __forceinline__ float block_reduce(float v, float* sh, bool is_max) {
    __syncthreads();
    int lane = threadIdx.x & 31, warp = threadIdx.x >> 5;
    #pragma unroll
    for (int o = 16; o > 0; o >>= 1) {
        float other = __shfl_down_sync(0xffffffffu, v, o);
        v = is_max ? fmaxf(v, other) : v + other;
    }
    if (lane == 0) sh[warp] = v;
    __syncthreads();
    int nw = blockDim.x >> 5;
    if (warp == 0) {
        v = (lane < nw) ? sh[lane] : (is_max ? -INFINITY : 0.f);
        #pragma unroll
        for (int o = 16; o > 0; o >>= 1) {
            float other = __shfl_down_sync(0xffffffffu, v, o);
            v = is_max ? fmaxf(v, other) : v + other;
        }
        if (lane == 0) sh[0] = v;
    }
    __syncthreads();
    return sh[0];
}

__device__ __forceinline__ float gelu_tanh(float v) {
    float v3 = v * v * v;
    return 0.5f * v * (1.f + tanhf(0.7978845608028654f * (v + 0.044715f * v3)));
}

__global__ void em_kernel(const float* __restrict__ e, const float* __restrict__ mod,
                          float* __restrict__ em) {
    int i = blockIdx.x * blockDim.x + threadIdx.x;
    if (i < 6 * C_DIM) em[i] = e[i] + mod[i];
}

__global__ void ln_mod_kernel(const float* __restrict__ x, const float* __restrict__ e0,
                              const float* __restrict__ e1, float* __restrict__ out) {
    __shared__ float sh[32];
    long long row = blockIdx.x;
    const float* xr = x + row * C_DIM;
    float s = 0.f, s2 = 0.f;
    for (int c = threadIdx.x; c < C_DIM; c += blockDim.x) {
        float v = xr[c];
        s += v; s2 += v * v;
    }
    float S  = block_reduce(s,  sh, false);
    float S2 = block_reduce(s2, sh, false);
    float m   = S  * (1.f / C_DIM);
    float var = S2 * (1.f / C_DIM) - m * m;
    float inv = rsqrtf(var + EPS);
    float* orow = out + row * C_DIM;
    for (int c = threadIdx.x; c < C_DIM; c += blockDim.x)
        orow[c] = e0[c] + (xr[c] - m) * inv * (1.f + e1[c]);
}

__global__ void rms_kernel(float* __restrict__ x, const float* __restrict__ w) {
    __shared__ float sh[32];
    long long row = blockIdx.x;
    float* xr = x + row * C_DIM;
    float s2 = 0.f;
    for (int c = threadIdx.x; c < C_DIM; c += blockDim.x) {
        float v = xr[c];
        s2 += v * v;
    }
    float S2 = block_reduce(s2, sh, false);
    float inv = rsqrtf(S2 * (1.f / C_DIM) + EPS);
    for (int c = threadIdx.x; c < C_DIM; c += blockDim.x)
        xr[c] = xr[c] * inv * w[c];
}

__global__ void rope_kernel(float* __restrict__ x, const float* __restrict__ freqs) {
    long long idx = (long long)blockIdx.x * blockDim.x + threadIdx.x;
    if (idx >= (long long)L_Q * NH * 64) return;
    int j = (int)(idx & 63);
    int n = (int)((idx >> 6) % NH);
    int l = (int)(idx / (64 * NH));
    int f  = l / 1200;
    int rm = l % 1200;
    int hh = rm / 40;
    int ww = rm % 40;
    int pos = (j < 22) ? f : ((j < 43) ? hh : ww);
    float cs = freqs[(pos * 64 + j) * 2 + 0];
    float sn = freqs[(pos * 64 + j) * 2 + 1];
    float* p = x + (long long)l * C_DIM + n * HD + 2 * j;
    float a = p[0], b = p[1];
    p[0] = a * cs - b * sn;
    p[1] = a * sn + b * cs;
}

__global__ void softmax_kernel(float* __restrict__ s, int lk) {
    __shared__ float sh[32];
    long long row = blockIdx.x;
    float* p = s + row * (long long)lk;
    float mx = -INFINITY;
    for (int i = threadIdx.x; i < lk; i += blockDim.x) mx = fmaxf(mx, p[i]);
    mx = block_reduce(mx, sh, true);
    float sum = 0.f;
    for (int i = threadIdx.x; i < lk; i += blockDim.x) {
        float e = __expf(p[i] - mx);
        p[i] = e; sum += e;
    }
    sum = block_reduce(sum, sh, false);
    float inv = 1.f / sum;
    for (int i = threadIdx.x; i < lk; i += blockDim.x) p[i] *= inv;
}

__global__ void residual_mul_kernel(const float* __restrict__ xin, const float* __restrict__ t,
                                    const float* __restrict__ ecol, float* __restrict__ out) {
    long long i = (long long)blockIdx.x * blockDim.x + threadIdx.x;
    if (i < (long long)L_Q * C_DIM) out[i] = xin[i] + t[i] * ecol[i % C_DIM];
}

__global__ void add_inplace_kernel(float* __restrict__ x, const float* __restrict__ t) {
    long long i = (long long)blockIdx.x * blockDim.x + threadIdx.x;
    if (i < (long long)L_Q * C_DIM) x[i] += t[i];
}

__global__ void addmul_inplace_kernel(float* __restrict__ x, const float* __restrict__ t,
                                      const float* __restrict__ ecol) {
    long long i = (long long)blockIdx.x * blockDim.x + threadIdx.x;
    if (i < (long long)L_Q * C_DIM) x[i] += t[i] * ecol[i % C_DIM];
}

// =====================================================================
// Split-bf16 HMMA GEMM (mma.sync, target-portable tensor cores)
//   C = act(scale * A@B + bias)
//   A: [M,K] fp32 row-major.  B: bKN=1 -> [K,N];  bKN=0 -> [N,K].
//   Tile 128x128x32, 256 threads (2x4 warps of 64x32), double-buffered.
//   Requires K % 32 == 0 (true for all shapes here).
// =====================================================================
#define ROWB 80            // smem row stride bytes (40 bf16): 5*16B -> ldmatrix conflict-free
#define CH_A_H 0
#define CH_A_L 10240
#define CH_B_H 20480
#define CH_B_L 30720
#define STAGE_BYTES 40960
#define HG_SMEM (2 * STAGE_BYTES)

static __device__ __forceinline__ uint32_t smem_u32(const void* p) {
    uint32_t r;
    asm("{ .reg .u64 t; cvta.to.shared.u64 t, %1; cvt.u32.u64 %0, t; }" : "=r"(r) : "l"(p));
    return r;
}
static __device__ __forceinline__ void sts64(uint32_t a, uint32_t x, uint32_t y) {
    asm volatile("st.shared.v2.b32 [%0], {%1,%2};" :: "r"(a), "r"(x), "r"(y));
}
static __device__ __forceinline__ void split_bf16(float v, unsigned short& h, unsigned short& l) {
    __nv_bfloat16 hb = __float2bfloat16_rn(v);
    float r = v - __bfloat162float(hb);
    __nv_bfloat16 lb = __float2bfloat16_rn(r);
    h = *reinterpret_cast<unsigned short*>(&hb);
    l = *reinterpret_cast<unsigned short*>(&lb);
}
static __device__ __forceinline__ void ldm_x4(uint32_t* r, uint32_t addr) {
    asm volatile("ldmatrix.sync.aligned.m8n8.x4.shared.b16 {%0,%1,%2,%3}, [%4];"
                 : "=r"(r[0]), "=r"(r[1]), "=r"(r[2]), "=r"(r[3]) : "r"(addr));
}
static __device__ __forceinline__ void ldm_x2(uint32_t* r, uint32_t addr) {
    asm volatile("ldmatrix.sync.aligned.m8n8.x2.shared.b16 {%0,%1}, [%2];"
                 : "=r"(r[0]), "=r"(r[1]) : "r"(addr));
}
static __device__ __forceinline__ void mma16816(float* c, const uint32_t* a, const uint32_t* b) {
    asm volatile("mma.sync.aligned.m16n8k16.row.col.f32.bf16.bf16.f32 "
                 "{%0,%1,%2,%3}, {%4,%5,%6,%7}, {%8,%9}, {%0,%1,%2,%3};"
                 : "+f"(c[0]), "+f"(c[1]), "+f"(c[2]), "+f"(c[3])
                 : "r"(a[0]), "r"(a[1]), "r"(a[2]), "r"(a[3]), "r"(b[0]), "r"(b[1]));
}

__global__ void __launch_bounds__(256, 1)
hgemm_kernel(const float* __restrict__ A, int lda, long long sAz,
             const float* __restrict__ B, int ldb, long long sBz,
             float* __restrict__ C, int ldc, long long sCz,
             int M, int N, int K,
             const float* __restrict__ bias, float scale, int act, int bKN) {
    extern __shared__ char smem[];
    uint32_t sbase = smem_u32(smem);

    int tid = threadIdx.x, lane = tid & 31, warp = tid >> 5;
    int wm = warp & 1, wn = warp >> 1;        // 2 x 4 warp grid

    A += (long long)blockIdx.z * sAz;
    B += (long long)blockIdx.z * sBz;
    C += (long long)blockIdx.z * sCz;

    int bm = blockIdx.y * 128;
    int bn = blockIdx.x * 128;
    int mRem = M - bm; if (mRem > 128) mRem = 128;
    int nRem = N - bn; if (nRem > 128) nRem = 128;

    const float* Ap = A + (long long)bm * lda;
    const float* Bp = bKN ? (B + bn) : (B + (long long)bn * ldb);

    // ldmatrix lane offsets
    int mat = lane >> 3, r8 = lane & 7;
    uint32_t a_off = (uint32_t)((wm * 64 + (mat & 1) * 8 + r8) * ROWB + (mat >> 1) * 16);
    int lv = lane & 15;
    uint32_t b_off = (uint32_t)((wn * 32 + (lv & 7)) * ROWB + (lv >> 3) * 16);

    float acc[4][4][4];
    #pragma unroll
    for (int mi = 0; mi < 4; mi++)
        #pragma unroll
        for (int ni = 0; ni < 4; ni++)
            #pragma unroll
            for (int q = 0; q < 4; q++) acc[mi][ni][q] = 0.f;

    float pa[16], pb[16];

    auto loadA = [&](int kc) {
        int k0 = kc << 5;
        #pragma unroll
        for (int i = 0; i < 4; i++) {
            int idx = tid + i * 256;
            int row = idx >> 3, kk = (idx & 7) << 2;
            float4 v = make_float4(0.f, 0.f, 0.f, 0.f);
            if (row < mRem)
                v = *reinterpret_cast<const float4*>(Ap + (long long)row * lda + k0 + kk);
            pa[i*4+0] = v.x; pa[i*4+1] = v.y; pa[i*4+2] = v.z; pa[i*4+3] = v.w;
        }
    };
    auto loadB = [&](int kc) {
        int k0 = kc << 5;
        if (!bKN) {
            #pragma unroll
            for (int i = 0; i < 4; i++) {
                int idx = tid + i * 256;
                int row = idx >> 3, kk = (idx & 7) << 2;
                float4 v = make_float4(0.f, 0.f, 0.f, 0.f);
                if (row < nRem)
                    v = *reinterpret_cast<const float4*>(Bp + (long long)row * ldb + k0 + kk);
                pb[i*4+0] = v.x; pb[i*4+1] = v.y; pb[i*4+2] = v.z; pb[i*4+3] = v.w;
            }
        } else {
            #pragma unroll
            for (int i = 0; i < 4; i++) {
                int idx = tid + i * 256;
                int n = idx & 127, k = (idx >> 7) << 2;
                #pragma unroll
                for (int j = 0; j < 4; j++)
                    pb[i*4+j] = (n < nRem) ? Bp[(long long)(k0 + k + j) * ldb + n] : 0.f;
            }
        }
    };
    auto stsA = [&](uint32_t sb) {
        #pragma unroll
        for (int i = 0; i < 4; i++) {
            int idx = tid + i * 256;
            int row = idx >> 3, kk = (idx & 7) << 2;
            unsigned short h[4], l[4];
            #pragma unroll
            for (int j = 0; j < 4; j++) split_bf16(pa[i*4+j], h[j], l[j]);
            uint32_t addr = sb + (uint32_t)(row * ROWB + kk * 2);
            sts64(addr + CH_A_H, (uint32_t)h[0] | ((uint32_t)h[1] << 16),
                                 (uint32_t)h[2] | ((uint32_t)h[3] << 16));
            sts64(addr + CH_A_L, (uint32_t)l[0] | ((uint32_t)l[1] << 16),
                                 (uint32_t)l[2] | ((uint32_t)l[3] << 16));
        }
    };
    auto stsB = [&](uint32_t sb) {
        #pragma unroll
        for (int i = 0; i < 4; i++) {
            int idx = tid + i * 256;
            int row, kk;
            if (!bKN) { row = idx >> 3; kk = (idx & 7) << 2; }
            else      { row = idx & 127; kk = (idx >> 7) << 2; }
            unsigned short h[4], l[4];
            #pragma unroll
            for (int j = 0; j < 4; j++) split_bf16(pb[i*4+j], h[j], l[j]);
            uint32_t addr = sb + (uint32_t)(row * ROWB + kk * 2);
            sts64(addr + CH_B_H, (uint32_t)h[0] | ((uint32_t)h[1] << 16),
                                 (uint32_t)h[2] | ((uint32_t)h[3] << 16));
            sts64(addr + CH_B_L, (uint32_t)l[0] | ((uint32_t)l[1] << 16),
                                 (uint32_t)l[2] | ((uint32_t)l[3] << 16));
        }
    };
    auto compute = [&](uint32_t sb) {
        #pragma unroll
        for (int kk2 = 0; kk2 < 2; kk2++) {
            uint32_t ksb = (uint32_t)(kk2 * 32);     // 16 bf16 * 2 bytes
            uint32_t aH[4][4], aL[4][4], bH[4][2], bL[4][2];
            #pragma unroll
            for (int mi = 0; mi < 4; mi++) {
                uint32_t ad = sb + mi * (16 * ROWB) + ksb + a_off;
                ldm_x4(aH[mi], ad + CH_A_H);
                ldm_x4(aL[mi], ad + CH_A_L);
            }
            #pragma unroll
            for (int ni = 0; ni < 4; ni++) {
                uint32_t bd = sb + ni * (8 * ROWB) + ksb + b_off;
                ldm_x2(bH[ni], bd + CH_B_H);
                ldm_x2(bL[ni], bd + CH_B_L);
            }
            #pragma unroll
            for (int mi = 0; mi < 4; mi++)
                #pragma unroll
                for (int ni = 0; ni < 4; ni++)
                    mma16816(acc[mi][ni], aH[mi], bH[ni]);
            #pragma unroll
            for (int mi = 0; mi < 4; mi++)
                #pragma unroll
                for (int ni = 0; ni < 4; ni++)
                    mma16816(acc[mi][ni], aH[mi], bL[ni]);
            #pragma unroll
            for (int mi = 0; mi < 4; mi++)
                #pragma unroll
                for (int ni = 0; ni < 4; ni++)
                    mma16816(acc[mi][ni], aL[mi], bH[ni]);
        }
    };

    int nc = K >> 5;

    loadA(0); loadB(0);
    stsA(sbase); stsB(sbase);
    __syncthreads();

    for (int c = 0; c < nc; c++) {
        uint32_t cur = sbase + (uint32_t)((c & 1) * STAGE_BYTES);
        if (c + 1 < nc) { loadA(c + 1); loadB(c + 1); }
        compute(cur);
        if (c + 1 < nc) {
            uint32_t nxt = sbase + (uint32_t)(((c + 1) & 1) * STAGE_BYTES);
            stsA(nxt); stsB(nxt);
            __syncthreads();
        }
    }

    // ---- epilogue: registers -> gmem ----
    int row0 = lane >> 2;
    int col0 = (lane & 3) * 2;
    #pragma unroll
    for (int mi = 0; mi < 4; mi++) {
        #pragma unroll
        for (int ni = 0; ni < 4; ni++) {
            int gn = bn + wn * 32 + ni * 8 + col0;
            if (gn >= N) continue;
            float b0 = 0.f, b1 = 0.f;
            if (bias) { b0 = bias[gn]; b1 = bias[gn + 1]; }
            int gm = bm + wm * 64 + mi * 16 + row0;
            float* c = acc[mi][ni];
            if (gm < M) {
                float v0 = c[0] * scale + b0;
                float v1 = c[1] * scale + b1;
                if (act == 1) { v0 = gelu_tanh(v0); v1 = gelu_tanh(v1); }
                *reinterpret_cast<float2*>(C + (long long)gm * ldc + gn) = make_float2(v0, v1);
            }
            if (gm + 8 < M) {
                float v0 = c[2] * scale + b0;
                float v1 = c[3] * scale + b1;
                if (act == 1) { v0 = gelu_tanh(v0); v1 = gelu_tanh(v1); }
                *reinterpret_cast<float2*>(C + (long long)(gm + 8) * ldc + gn) = make_float2(v0, v1);
            }
        }
    }
}

// ---------------- host ----------------
static void hgemm(const float* A, int lda, long long sAz,
                  const float* B, int ldb, long long sBz,
                  float* C, int ldc, long long sCz,
                  int M, int N, int K, int Z,
                  const float* bias, float scale, int act, int bKN) {
    dim3 grid((N + 127) / 128, (M + 127) / 128, Z);
    hgemm_kernel<<<grid, 256, HG_SMEM>>>(A, lda, sAz, B, ldb, sBz, C, ldc, sCz,
                                         M, N, K, bias, scale, act, bKN);
}

extern "C" void kernel_launch(void* const* d_in, const int* in_sizes, int n_in,
                              void* d_out, int out_size) {
    const float* x        = (const float*)d_in[0];
    const float* e        = (const float*)d_in[1];
    const float* context  = (const float*)d_in[2];
    const float* freqs    = (const float*)d_in[3];
    const float* modulation = (const float*)d_in[7];
    const float* sa_q_w = (const float*)d_in[8];
    const float* sa_q_b = (const float*)d_in[9];
    const float* sa_k_w = (const float*)d_in[10];
    const float* sa_k_b = (const float*)d_in[11];
    const float* sa_v_w = (const float*)d_in[12];
    const float* sa_v_b = (const float*)d_in[13];
    const float* sa_o_w = (const float*)d_in[14];
    const float* sa_o_b = (const float*)d_in[15];
    const float* sa_nq_w = (const float*)d_in[16];
    const float* sa_nk_w = (const float*)d_in[17];
    const float* ca_q_w = (const float*)d_in[18];
    const float* ca_q_b = (const float*)d_in[19];
    const float* ca_k_w = (const float*)d_in[20];
    const float* ca_k_b = (const float*)d_in[21];
    const float* ca_v_w = (const float*)d_in[22];
    const float* ca_v_b = (const float*)d_in[23];
    const float* ca_o_w = (const float*)d_in[24];
    const float* ca_o_b = (const float*)d_in[25];
    const float* ca_nq_w = (const float*)d_in[26];
    const float* ca_nk_w = (const float*)d_in[27];
    const float* ffn_w1 = (const float*)d_in[28];
    const float* ffn_b1 = (const float*)d_in[29];
    const float* ffn_w2 = (const float*)d_in[30];
    const float* ffn_b2 = (const float*)d_in[31];
    float* out = (float*)d_out;

    cudaFuncSetAttribute(hgemm_kernel,
                         cudaFuncAttributeMaxDynamicSharedMemorySize, HG_SMEM);

    float *em, *h, *q, *k, *v, *y, *t, *s, *ff;
    cudaGetSymbolAddress((void**)&em, g_em);
    cudaGetSymbolAddress((void**)&h,  g_h);
    cudaGetSymbolAddress((void**)&q,  g_q);
    cudaGetSymbolAddress((void**)&k,  g_k);
    cudaGetSymbolAddress((void**)&v,  g_v);
    cudaGetSymbolAddress((void**)&y,  g_y);
    cudaGetSymbolAddress((void**)&t,  g_t);
    cudaGetSymbolAddress((void**)&s,  g_s);
    cudaGetSymbolAddress((void**)&ff, g_ff);

    const float ascale = 0.08838834764831845f;  // 1/sqrt(128)
    const long long LC = (long long)L_Q * C_DIM;
    int eltBlocks = (int)((LC + 255) / 256);
    int ropeBlocks = (int)(((long long)L_Q * NH * 64 + 255) / 256);

    em_kernel<<<(6 * C_DIM + 255) / 256, 256>>>(e, modulation, em);

    // ---- self attention ----
    ln_mod_kernel<<<L_Q, 256>>>(x, em + 0 * C_DIM, em + 1 * C_DIM, h);
    hgemm(h, C_DIM, 0, sa_q_w, C_DIM, 0, q, C_DIM, 0, L_Q, C_DIM, C_DIM, 1, sa_q_b, 1.f, 0, 1);
    hgemm(h, C_DIM, 0, sa_k_w, C_DIM, 0, k, C_DIM, 0, L_Q, C_DIM, C_DIM, 1, sa_k_b, 1.f, 0, 1);
    hgemm(h, C_DIM, 0, sa_v_w, C_DIM, 0, v, C_DIM, 0, L_Q, C_DIM, C_DIM, 1, sa_v_b, 1.f, 0, 1);
    rms_kernel<<<L_Q, 256>>>(q, sa_nq_w);
    rms_kernel<<<L_Q, 256>>>(k, sa_nk_w);
    rope_kernel<<<ropeBlocks, 256>>>(q, freqs);
    rope_kernel<<<ropeBlocks, 256>>>(k, freqs);
    // scores = scale * Q @ K^T per head  (K matrix is [N,K] -> bKN=0)
    hgemm(q, C_DIM, HD, k, C_DIM, HD, s, L_Q, (long long)L_Q * L_Q,
          L_Q, L_Q, HD, NH, nullptr, ascale, 0, 0);
    softmax_kernel<<<NH * L_Q, 256>>>(s, L_Q);
    // y = P @ V per head  (V is [K,N] -> bKN=1)
    hgemm(s, L_Q, (long long)L_Q * L_Q, v, C_DIM, HD, y, C_DIM, HD,
          L_Q, HD, L_Q, NH, nullptr, 1.f, 0, 1);
    hgemm(y, C_DIM, 0, sa_o_w, C_DIM, 0, t, C_DIM, 0, L_Q, C_DIM, C_DIM, 1, sa_o_b, 1.f, 0, 1);
    residual_mul_kernel<<<eltBlocks, 256>>>(x, t, em + 2 * C_DIM, out);

    // ---- cross attention ----
    hgemm(out, C_DIM, 0, ca_q_w, C_DIM, 0, q, C_DIM, 0, L_Q, C_DIM, C_DIM, 1, ca_q_b, 1.f, 0, 1);
    rms_kernel<<<L_Q, 256>>>(q, ca_nq_w);
    hgemm(context, C_DIM, 0, ca_k_w, C_DIM, 0, k, C_DIM, 0, L_KV, C_DIM, C_DIM, 1, ca_k_b, 1.f, 0, 1);
    rms_kernel<<<L_KV, 256>>>(k, ca_nk_w);
    hgemm(context, C_DIM, 0, ca_v_w, C_DIM, 0, v, C_DIM, 0, L_KV, C_DIM, C_DIM, 1, ca_v_b, 1.f, 0, 1);
    hgemm(q, C_DIM, HD, k, C_DIM, HD, s, L_KV, (long long)L_Q * L_KV,
          L_Q, L_KV, HD, NH, nullptr, ascale, 0, 0);
    softmax_kernel<<<NH * L_Q, 256>>>(s, L_KV);
    hgemm(s, L_KV, (long long)L_Q * L_KV, v, C_DIM, HD, y, C_DIM, HD,
          L_Q, HD, L_KV, NH, nullptr, 1.f, 0, 1);
    hgemm(y, C_DIM, 0, ca_o_w, C_DIM, 0, t, C_DIM, 0, L_Q, C_DIM, C_DIM, 1, ca_o_b, 1.f, 0, 1);
    add_inplace_kernel<<<eltBlocks, 256>>>(out, t);

    // ---- FFN ----
    ln_mod_kernel<<<L_Q, 256>>>(out, em + 3 * C_DIM, em + 4 * C_DIM, h);
    hgemm(h, C_DIM, 0, ffn_w1, FF_DIM, 0, ff, FF_DIM, 0,
          L_Q, FF_DIM, C_DIM, 1, ffn_b1, 1.f, 1, 1);         // + GELU
    hgemm(ff, FF_DIM, 0, ffn_w2, C_DIM, 0, t, C_DIM, 0,
          L_Q, C_DIM, FF_DIM, 1, ffn_b2, 1.f, 0, 1);
    addmul_inplace_kernel<<<eltBlocks, 256>>>(out, t, em + 5 * C_DIM);
}

// round 5
// speedup vs baseline: 3.4059x; 1.3909x over previous
#include <cuda_runtime.h>
#include <cuda_bf16.h>
#include <stdint.h>
#include <math.h>

// Problem constants
#define C_DIM 1536
#define L_Q   2400
#define L_KV  512
#define NH    12
#define HD    128
#define FF_DIM 8960
#define EPS   1e-6f

// ---------------- device scratch ----------------
__device__ __align__(256) float g_em[6 * C_DIM];
__device__ __align__(256) float g_q [L_Q * C_DIM];
__device__ __align__(256) float g_k [L_Q * C_DIM];
__device__ __align__(256) float g_v [L_Q * C_DIM];
__device__ __align__(256) float g_t [L_Q * C_DIM];
__device__ __align__(256) float g_s [NH * L_Q * L_Q];          // fp32 scores
// bf16 hi/lo operand buffers (as ushort)
__device__ __align__(256) unsigned short g_hh[L_Q * C_DIM], g_hl[L_Q * C_DIM];
__device__ __align__(256) unsigned short g_qh[L_Q * C_DIM], g_ql[L_Q * C_DIM];
__device__ __align__(256) unsigned short g_kh[L_Q * C_DIM], g_kl[L_Q * C_DIM];
__device__ __align__(256) unsigned short g_vth[C_DIM * L_Q], g_vtl[C_DIM * L_Q];
__device__ __align__(256) unsigned short g_yh[L_Q * C_DIM], g_yl[L_Q * C_DIM];
__device__ __align__(256) unsigned short g_oh[L_Q * C_DIM], g_ol[L_Q * C_DIM];
__device__ __align__(256) unsigned short g_cxh[L_KV * C_DIM], g_cxl[L_KV * C_DIM];
__device__ __align__(256) unsigned short g_ph[NH * L_Q * L_Q], g_pl[NH * L_Q * L_Q];
__device__ __align__(256) unsigned short g_ffh[L_Q * FF_DIM], g_ffl[L_Q * FF_DIM];
__device__ __align__(256) unsigned short g_wh[FF_DIM * C_DIM], g_wl[FF_DIM * C_DIM];

// ---------------- helpers ----------------
__device__ __forceinline__ float block_reduce(float v, float* sh, bool is_max) {
    __syncthreads();
    int lane = threadIdx.x & 31, warp = threadIdx.x >> 5;
    #pragma unroll
    for (int o = 16; o > 0; o >>= 1) {
        float other = __shfl_down_sync(0xffffffffu, v, o);
        v = is_max ? fmaxf(v, other) : v + other;
    }
    if (lane == 0) sh[warp] = v;
    __syncthreads();
    int nw = blockDim.x >> 5;
    if (warp == 0) {
        v = (lane < nw) ? sh[lane] : (is_max ? -INFINITY : 0.f);
        #pragma unroll
        for (int o = 16; o > 0; o >>= 1) {
            float other = __shfl_down_sync(0xffffffffu, v, o);
            v = is_max ? fmaxf(v, other) : v + other;
        }
        if (lane == 0) sh[0] = v;
    }
    __syncthreads();
    return sh[0];
}

__device__ __forceinline__ float gelu_tanh(float v) {
    float v3 = v * v * v;
    return 0.5f * v * (1.f + tanhf(0.7978845608028654f * (v + 0.044715f * v3)));
}

static __device__ __forceinline__ void split_bf16(float v, unsigned short& h, unsigned short& l) {
    __nv_bfloat16 hb = __float2bfloat16_rn(v);
    float r = v - __bfloat162float(hb);
    __nv_bfloat16 lb = __float2bfloat16_rn(r);
    h = *reinterpret_cast<unsigned short*>(&hb);
    l = *reinterpret_cast<unsigned short*>(&lb);
}

// ---------------- elementwise / norm kernels ----------------
__global__ void em_kernel(const float* __restrict__ e, const float* __restrict__ mod,
                          float* __restrict__ em) {
    int i = blockIdx.x * blockDim.x + threadIdx.x;
    if (i < 6 * C_DIM) em[i] = e[i] + mod[i];
}

// LN + modulation, write bf16 hi/lo only
__global__ void ln_mod_split_kernel(const float* __restrict__ x, const float* __restrict__ e0,
                                    const float* __restrict__ e1,
                                    unsigned short* __restrict__ oh, unsigned short* __restrict__ ol) {
    __shared__ float sh[32];
    long long row = blockIdx.x;
    const float* xr = x + row * C_DIM;
    float s = 0.f, s2 = 0.f;
    for (int c = threadIdx.x; c < C_DIM; c += blockDim.x) {
        float v = xr[c];
        s += v; s2 += v * v;
    }
    float S  = block_reduce(s,  sh, false);
    float S2 = block_reduce(s2, sh, false);
    float m   = S  * (1.f / C_DIM);
    float var = S2 * (1.f / C_DIM) - m * m;
    float inv = rsqrtf(var + EPS);
    for (int c = threadIdx.x; c < C_DIM; c += blockDim.x) {
        float v = e0[c] + (xr[c] - m) * inv * (1.f + e1[c]);
        unsigned short h, l; split_bf16(v, h, l);
        oh[row * C_DIM + c] = h;
        ol[row * C_DIM + c] = l;
    }
}

__global__ void rms_kernel(float* __restrict__ x, const float* __restrict__ w) {
    __shared__ float sh[32];
    long long row = blockIdx.x;
    float* xr = x + row * C_DIM;
    float s2 = 0.f;
    for (int c = threadIdx.x; c < C_DIM; c += blockDim.x) {
        float v = xr[c];
        s2 += v * v;
    }
    float S2 = block_reduce(s2, sh, false);
    float inv = rsqrtf(S2 * (1.f / C_DIM) + EPS);
    for (int c = threadIdx.x; c < C_DIM; c += blockDim.x)
        xr[c] = xr[c] * inv * w[c];
}

__global__ void rope_kernel(float* __restrict__ x, const float* __restrict__ freqs) {
    long long idx = (long long)blockIdx.x * blockDim.x + threadIdx.x;
    if (idx >= (long long)L_Q * NH * 64) return;
    int j = (int)(idx & 63);
    int n = (int)((idx >> 6) % NH);
    int l = (int)(idx / (64 * NH));
    int f  = l / 1200;
    int rm = l % 1200;
    int hh = rm / 40;
    int ww = rm % 40;
    int pos = (j < 22) ? f : ((j < 43) ? hh : ww);
    float cs = freqs[(pos * 64 + j) * 2 + 0];
    float sn = freqs[(pos * 64 + j) * 2 + 1];
    float* p = x + (long long)l * C_DIM + n * HD + 2 * j;
    float a = p[0], b = p[1];
    p[0] = a * cs - b * sn;
    p[1] = a * sn + b * cs;
}

// fp32 -> bf16 hi/lo elementwise
__global__ void conv_split_kernel(const float* __restrict__ src, long long n,
                                  unsigned short* __restrict__ dh, unsigned short* __restrict__ dl) {
    long long i = (long long)blockIdx.x * blockDim.x + threadIdx.x;
    if (i < n) {
        unsigned short h, l; split_bf16(src[i], h, l);
        dh[i] = h; dl[i] = l;
    }
}

// [R, Ccol] fp32 -> [Ccol, R] bf16 hi/lo  (all dims % 32 == 0)
__global__ void transpose_split_kernel(const float* __restrict__ src, int R, int Ccol,
                                       unsigned short* __restrict__ dh, unsigned short* __restrict__ dl) {
    __shared__ float tile[32][33];
    int bx = blockIdx.x, by = blockIdx.y;
    int tx = threadIdx.x, ty = threadIdx.y;  // 32 x 8
    #pragma unroll
    for (int i = 0; i < 4; i++) {
        int r = by * 32 + ty + i * 8;
        tile[ty + i * 8][tx] = src[(long long)r * Ccol + bx * 32 + tx];
    }
    __syncthreads();
    #pragma unroll
    for (int i = 0; i < 4; i++) {
        int ro = bx * 32 + ty + i * 8;   // output row (= src col)
        int co = by * 32 + tx;           // output col (= src row)
        float v = tile[tx][ty + i * 8];
        unsigned short h, l; split_bf16(v, h, l);
        dh[(long long)ro * R + co] = h;
        dl[(long long)ro * R + co] = l;
    }
}

// softmax over fp32 row, emit bf16 hi/lo probabilities
__global__ void softmax_split_kernel(const float* __restrict__ s, int lk,
                                     unsigned short* __restrict__ ph, unsigned short* __restrict__ pl) {
    __shared__ float sh[32];
    long long row = blockIdx.x;
    const float* p = s + row * (long long)lk;
    float mx = -INFINITY;
    for (int i = threadIdx.x; i < lk; i += blockDim.x) mx = fmaxf(mx, p[i]);
    mx = block_reduce(mx, sh, true);
    float sum = 0.f;
    for (int i = threadIdx.x; i < lk; i += blockDim.x) sum += __expf(p[i] - mx);
    sum = block_reduce(sum, sh, false);
    float inv = 1.f / sum;
    for (int i = threadIdx.x; i < lk; i += blockDim.x) {
        float v = __expf(p[i] - mx) * inv;
        unsigned short h, l; split_bf16(v, h, l);
        ph[row * (long long)lk + i] = h;
        pl[row * (long long)lk + i] = l;
    }
}

// out = xin + t*e; also emit bf16 hi/lo of out
__global__ void residual_mul_conv_kernel(const float* __restrict__ xin, const float* __restrict__ t,
                                         const float* __restrict__ ecol, float* __restrict__ out,
                                         unsigned short* __restrict__ oh, unsigned short* __restrict__ ol) {
    long long i = (long long)blockIdx.x * blockDim.x + threadIdx.x;
    if (i < (long long)L_Q * C_DIM) {
        float v = xin[i] + t[i] * ecol[i % C_DIM];
        out[i] = v;
        unsigned short h, l; split_bf16(v, h, l);
        oh[i] = h; ol[i] = l;
    }
}

__global__ void add_inplace_kernel(float* __restrict__ x, const float* __restrict__ t) {
    long long i = (long long)blockIdx.x * blockDim.x + threadIdx.x;
    if (i < (long long)L_Q * C_DIM) x[i] += t[i];
}

__global__ void addmul_inplace_kernel(float* __restrict__ x, const float* __restrict__ t,
                                      const float* __restrict__ ecol) {
    long long i = (long long)blockIdx.x * blockDim.x + threadIdx.x;
    if (i < (long long)L_Q * C_DIM) x[i] += t[i] * ecol[i % C_DIM];
}

// =====================================================================
// Split-bf16 HMMA GEMM, pre-converted operands + cp.async 3-stage pipeline.
//   A: [M,K] bf16 hi/lo, row-major (lda elems, z-stride sAz)
//   B: [N,K] bf16 hi/lo, K-major   (ldb elems, z-stride sBz)
//   C: optional fp32 / optional bf16 hi/lo  (ldc, z-stride sCz)
//   Tile 128x128x64, 256 threads (2x4 warps of 64x32).
// =====================================================================
#define STAGES 3
#define STG_BYTES 65536          // 4 arrays * 16KB (128 rows * 128B)
#define SA_H 0
#define SA_L 16384
#define SB_H 32768
#define SB_L 49152
#define HG_SMEM (STAGES * STG_BYTES)

static __device__ __forceinline__ uint32_t smem_u32(const void* p) {
    uint32_t r;
    asm("{ .reg .u64 t; cvta.to.shared.u64 t, %1; cvt.u32.u64 %0, t; }" : "=r"(r) : "l"(p));
    return r;
}
static __device__ __forceinline__ void cpa16(uint32_t s, const void* g, uint32_t sz) {
    asm volatile("cp.async.cg.shared.global [%0], [%1], 16, %2;" :: "r"(s), "l"(g), "r"(sz));
}
static __device__ __forceinline__ void cpa_commit() {
    asm volatile("cp.async.commit_group;");
}
static __device__ __forceinline__ void cpa_wait1() {
    asm volatile("cp.async.wait_group 1;");
}
static __device__ __forceinline__ void ldm_x4(uint32_t* r, uint32_t addr) {
    asm volatile("ldmatrix.sync.aligned.m8n8.x4.shared.b16 {%0,%1,%2,%3}, [%4];"
                 : "=r"(r[0]), "=r"(r[1]), "=r"(r[2]), "=r"(r[3]) : "r"(addr));
}
static __device__ __forceinline__ void mma16816(float* c, const uint32_t* a, uint32_t b0, uint32_t b1) {
    asm volatile("mma.sync.aligned.m16n8k16.row.col.f32.bf16.bf16.f32 "
                 "{%0,%1,%2,%3}, {%4,%5,%6,%7}, {%8,%9}, {%0,%1,%2,%3};"
                 : "+f"(c[0]), "+f"(c[1]), "+f"(c[2]), "+f"(c[3])
                 : "r"(a[0]), "r"(a[1]), "r"(a[2]), "r"(a[3]), "r"(b0), "r"(b1));
}

__global__ void __launch_bounds__(256, 1)
hgemm2_kernel(const unsigned short* __restrict__ Ah, const unsigned short* __restrict__ Al,
              int lda, long long sAz,
              const unsigned short* __restrict__ Bh, const unsigned short* __restrict__ Bl,
              int ldb, long long sBz,
              float* __restrict__ Cf, unsigned short* __restrict__ Ch, unsigned short* __restrict__ Cl,
              int ldc, long long sCz,
              int M, int N, int K,
              const float* __restrict__ bias, float scale, int act) {
    extern __shared__ char smem[];
    uint32_t sbase = smem_u32(smem);

    int tid = threadIdx.x, lane = tid & 31, warp = tid >> 5;
    int wm = warp & 1, wn = warp >> 1;       // 2 x 4 warps

    long long zz = blockIdx.z;
    Ah += zz * sAz; Al += zz * sAz;
    Bh += zz * sBz; Bl += zz * sBz;
    if (Cf) Cf += zz * sCz;
    if (Ch) { Ch += zz * sCz; Cl += zz * sCz; }

    int bm = blockIdx.y * 128;
    int bn = blockIdx.x * 128;
    int mRem = M - bm; if (mRem > 128) mRem = 128;
    int nRem = N - bn; if (nRem > 128) nRem = 128;

    int nch = (K + 63) >> 6;

    // per-thread cp.async mapping: idx = tid + i*256 -> row(0..127), chunk(0..7)
    auto loadStage = [&](int c) {
        uint32_t sb = sbase + (uint32_t)((c % STAGES) * STG_BYTES);
        int k0 = c << 6;
        #pragma unroll
        for (int i = 0; i < 4; i++) {
            int idx = tid + i * 256;
            int row = idx >> 3;
            int ch = idx & 7;
            uint32_t soff = (uint32_t)(row * 128 + ((ch ^ (row & 7)) << 4));
            int gk = k0 + ch * 8;
            // A
            {
                bool ok = (row < mRem) && (gk < K);
                long long off = ok ? ((long long)(bm + row) * lda + gk) : 0;
                uint32_t sz = ok ? 16u : 0u;
                cpa16(sb + SA_H + soff, Ah + off, sz);
                cpa16(sb + SA_L + soff, Al + off, sz);
            }
            // B
            {
                bool ok = (row < nRem) && (gk < K);
                long long off = ok ? ((long long)(bn + row) * ldb + gk) : 0;
                uint32_t sz = ok ? 16u : 0u;
                cpa16(sb + SB_H + soff, Bh + off, sz);
                cpa16(sb + SB_L + soff, Bl + off, sz);
            }
        }
    };

    float acc[4][4][4];
    #pragma unroll
    for (int mi = 0; mi < 4; mi++)
        #pragma unroll
        for (int ni = 0; ni < 4; ni++)
            #pragma unroll
            for (int q = 0; q < 4; q++) acc[mi][ni][q] = 0.f;

    int frow = ((lane >> 3) & 1) * 8 + (lane & 7);  // ldmatrix row within 16
    int fhalf = lane >> 4;                           // chunk half (0/1)

    // prologue
    loadStage(0); cpa_commit();
    if (nch > 1) loadStage(1);
    cpa_commit();

    for (int c = 0; c < nch; c++) {
        cpa_wait1();
        __syncthreads();
        uint32_t sb = sbase + (uint32_t)((c % STAGES) * STG_BYTES);

        #pragma unroll
        for (int k16 = 0; k16 < 4; k16++) {
            uint32_t aH[4][4], aL[4][4], bH[2][4], bL[2][4];
            #pragma unroll
            for (int mi = 0; mi < 4; mi++) {
                int row = wm * 64 + mi * 16 + frow;
                int ch = k16 * 2 + fhalf;
                uint32_t off = (uint32_t)(row * 128 + ((ch ^ (row & 7)) << 4));
                ldm_x4(aH[mi], sb + SA_H + off);
                ldm_x4(aL[mi], sb + SA_L + off);
            }
            #pragma unroll
            for (int nj = 0; nj < 2; nj++) {
                int row = wn * 32 + nj * 16 + frow;
                int ch = k16 * 2 + fhalf;
                uint32_t off = (uint32_t)(row * 128 + ((ch ^ (row & 7)) << 4));
                ldm_x4(bH[nj], sb + SB_H + off);
                ldm_x4(bL[nj], sb + SB_L + off);
            }
            // acc order: ni = nj*2 + t, frag t=0: regs {r0,r2}, t=1: {r1,r3}
            #pragma unroll
            for (int mi = 0; mi < 4; mi++) {
                #pragma unroll
                for (int nj = 0; nj < 2; nj++) {
                    mma16816(acc[mi][nj*2+0], aH[mi], bH[nj][0], bH[nj][2]);
                    mma16816(acc[mi][nj*2+1], aH[mi], bH[nj][1], bH[nj][3]);
                    mma16816(acc[mi][nj*2+0], aH[mi], bL[nj][0], bL[nj][2]);
                    mma16816(acc[mi][nj*2+1], aH[mi], bL[nj][1], bL[nj][3]);
                    mma16816(acc[mi][nj*2+0], aL[mi], bH[nj][0], bH[nj][2]);
                    mma16816(acc[mi][nj*2+1], aL[mi], bH[nj][1], bH[nj][3]);
                }
            }
        }
        if (c + 2 < nch) loadStage(c + 2);
        cpa_commit();
    }

    // ---- epilogue ----
    int row0 = lane >> 2;
    int col0 = (lane & 3) * 2;
    #pragma unroll
    for (int mi = 0; mi < 4; mi++) {
        #pragma unroll
        for (int ni = 0; ni < 4; ni++) {
            int gn = bn + wn * 32 + ni * 8 + col0;
            if (gn >= N) continue;
            float b0 = 0.f, b1 = 0.f;
            if (bias) { b0 = bias[gn]; b1 = bias[gn + 1]; }
            float* cc = acc[mi][ni];
            #pragma unroll
            for (int half = 0; half < 2; half++) {
                int gm = bm + wm * 64 + mi * 16 + row0 + half * 8;
                if (gm >= M) continue;
                float v0 = cc[half * 2 + 0] * scale + b0;
                float v1 = cc[half * 2 + 1] * scale + b1;
                if (act == 1) { v0 = gelu_tanh(v0); v1 = gelu_tanh(v1); }
                long long o = (long long)gm * ldc + gn;
                if (Cf) *reinterpret_cast<float2*>(Cf + o) = make_float2(v0, v1);
                if (Ch) {
                    unsigned short h0, l0, h1, l1;
                    split_bf16(v0, h0, l0); split_bf16(v1, h1, l1);
                    *reinterpret_cast<ushort2*>(Ch + o) = make_ushort2(h0, h1);
                    *reinterpret_cast<ushort2*>(Cl + o) = make_ushort2(l0, l1);
                }
            }
        }
    }
}

// ---------------- host ----------------
static void hgemm2(const unsigned short* Ah, const unsigned short* Al, int lda, long long sAz,
                   const unsigned short* Bh, const unsigned short* Bl, int ldb, long long sBz,
                   float* Cf, unsigned short* Ch, unsigned short* Cl, int ldc, long long sCz,
                   int M, int N, int K, int Z, const float* bias, float scale, int act) {
    dim3 grid((N + 127) / 128, (M + 127) / 128, Z);
    hgemm2_kernel<<<grid, 256, HG_SMEM>>>(Ah, Al, lda, sAz, Bh, Bl, ldb, sBz,
                                          Cf, Ch, Cl, ldc, sCz, M, N, K, bias, scale, act);
}

static void trsplit(const float* src, int R, int Ccol, unsigned short* dh, unsigned short* dl) {
    dim3 grid(Ccol / 32, R / 32);
    transpose_split_kernel<<<grid, dim3(32, 8)>>>(src, R, Ccol, dh, dl);
}

extern "C" void kernel_launch(void* const* d_in, const int* in_sizes, int n_in,
                              void* d_out, int out_size) {
    const float* x        = (const float*)d_in[0];
    const float* e        = (const float*)d_in[1];
    const float* context  = (const float*)d_in[2];
    const float* freqs    = (const float*)d_in[3];
    const float* modulation = (const float*)d_in[7];
    const float* sa_q_w = (const float*)d_in[8];
    const float* sa_q_b = (const float*)d_in[9];
    const float* sa_k_w = (const float*)d_in[10];
    const float* sa_k_b = (const float*)d_in[11];
    const float* sa_v_w = (const float*)d_in[12];
    const float* sa_v_b = (const float*)d_in[13];
    const float* sa_o_w = (const float*)d_in[14];
    const float* sa_o_b = (const float*)d_in[15];
    const float* sa_nq_w = (const float*)d_in[16];
    const float* sa_nk_w = (const float*)d_in[17];
    const float* ca_q_w = (const float*)d_in[18];
    const float* ca_q_b = (const float*)d_in[19];
    const float* ca_k_w = (const float*)d_in[20];
    const float* ca_k_b = (const float*)d_in[21];
    const float* ca_v_w = (const float*)d_in[22];
    const float* ca_v_b = (const float*)d_in[23];
    const float* ca_o_w = (const float*)d_in[24];
    const float* ca_o_b = (const float*)d_in[25];
    const float* ca_nq_w = (const float*)d_in[26];
    const float* ca_nk_w = (const float*)d_in[27];
    const float* ffn_w1 = (const float*)d_in[28];
    const float* ffn_b1 = (const float*)d_in[29];
    const float* ffn_w2 = (const float*)d_in[30];
    const float* ffn_b2 = (const float*)d_in[31];
    float* out = (float*)d_out;

    cudaFuncSetAttribute(hgemm2_kernel,
                         cudaFuncAttributeMaxDynamicSharedMemorySize, HG_SMEM);

    float *em, *q, *k, *v, *t, *s;
    unsigned short *hh, *hl, *qh, *ql, *kh, *kl, *vth, *vtl, *yh, *yl;
    unsigned short *oh, *ol, *cxh, *cxl, *ph, *pl, *ffh, *ffl, *wh, *wl;
    cudaGetSymbolAddress((void**)&em, g_em);
    cudaGetSymbolAddress((void**)&q,  g_q);
    cudaGetSymbolAddress((void**)&k,  g_k);
    cudaGetSymbolAddress((void**)&v,  g_v);
    cudaGetSymbolAddress((void**)&t,  g_t);
    cudaGetSymbolAddress((void**)&s,  g_s);
    cudaGetSymbolAddress((void**)&hh, g_hh);  cudaGetSymbolAddress((void**)&hl, g_hl);
    cudaGetSymbolAddress((void**)&qh, g_qh);  cudaGetSymbolAddress((void**)&ql, g_ql);
    cudaGetSymbolAddress((void**)&kh, g_kh);  cudaGetSymbolAddress((void**)&kl, g_kl);
    cudaGetSymbolAddress((void**)&vth, g_vth); cudaGetSymbolAddress((void**)&vtl, g_vtl);
    cudaGetSymbolAddress((void**)&yh, g_yh);  cudaGetSymbolAddress((void**)&yl, g_yl);
    cudaGetSymbolAddress((void**)&oh, g_oh);  cudaGetSymbolAddress((void**)&ol, g_ol);
    cudaGetSymbolAddress((void**)&cxh, g_cxh); cudaGetSymbolAddress((void**)&cxl, g_cxl);
    cudaGetSymbolAddress((void**)&ph, g_ph);  cudaGetSymbolAddress((void**)&pl, g_pl);
    cudaGetSymbolAddress((void**)&ffh, g_ffh); cudaGetSymbolAddress((void**)&ffl, g_ffl);
    cudaGetSymbolAddress((void**)&wh, g_wh);  cudaGetSymbolAddress((void**)&wl, g_wl);

    const float ascale = 0.08838834764831845f;   // 1/sqrt(128)
    const long long LC = (long long)L_Q * C_DIM;
    int eltBlocks = (int)((LC + 255) / 256);
    int ropeBlocks = (int)(((long long)L_Q * NH * 64 + 255) / 256);

    em_kernel<<<(6 * C_DIM + 255) / 256, 256>>>(e, modulation, em);

    // ================= self attention =================
    ln_mod_split_kernel<<<L_Q, 256>>>(x, em + 0 * C_DIM, em + 1 * C_DIM, hh, hl);
    trsplit(sa_q_w, C_DIM, C_DIM, wh, wl);
    hgemm2(hh, hl, C_DIM, 0, wh, wl, C_DIM, 0, q, nullptr, nullptr, C_DIM, 0,
           L_Q, C_DIM, C_DIM, 1, sa_q_b, 1.f, 0);
    trsplit(sa_k_w, C_DIM, C_DIM, wh, wl);
    hgemm2(hh, hl, C_DIM, 0, wh, wl, C_DIM, 0, k, nullptr, nullptr, C_DIM, 0,
           L_Q, C_DIM, C_DIM, 1, sa_k_b, 1.f, 0);
    trsplit(sa_v_w, C_DIM, C_DIM, wh, wl);
    hgemm2(hh, hl, C_DIM, 0, wh, wl, C_DIM, 0, v, nullptr, nullptr, C_DIM, 0,
           L_Q, C_DIM, C_DIM, 1, sa_v_b, 1.f, 0);
    rms_kernel<<<L_Q, 256>>>(q, sa_nq_w);
    rms_kernel<<<L_Q, 256>>>(k, sa_nk_w);
    rope_kernel<<<ropeBlocks, 256>>>(q, freqs);
    rope_kernel<<<ropeBlocks, 256>>>(k, freqs);
    conv_split_kernel<<<eltBlocks, 256>>>(q, LC, qh, ql);
    conv_split_kernel<<<eltBlocks, 256>>>(k, LC, kh, kl);
    trsplit(v, L_Q, C_DIM, vth, vtl);                // V^T [C, L]
    // scores = scale * Q @ K^T per head
    hgemm2(qh, ql, C_DIM, HD, kh, kl, C_DIM, HD, s, nullptr, nullptr,
           L_Q, (long long)L_Q * L_Q, L_Q, L_Q, HD, NH, nullptr, ascale, 0);
    softmax_split_kernel<<<NH * L_Q, 256>>>(s, L_Q, ph, pl);
    // y = P @ V per head  (bf16 out only)
    hgemm2(ph, pl, L_Q, (long long)L_Q * L_Q, vth, vtl, L_Q, (long long)HD * L_Q,
           nullptr, yh, yl, C_DIM, HD, L_Q, HD, L_Q, NH, nullptr, 1.f, 0);
    trsplit(sa_o_w, C_DIM, C_DIM, wh, wl);
    hgemm2(yh, yl, C_DIM, 0, wh, wl, C_DIM, 0, t, nullptr, nullptr, C_DIM, 0,
           L_Q, C_DIM, C_DIM, 1, sa_o_b, 1.f, 0);
    residual_mul_conv_kernel<<<eltBlocks, 256>>>(x, t, em + 2 * C_DIM, out, oh, ol);

    // ================= cross attention =================
    trsplit(ca_q_w, C_DIM, C_DIM, wh, wl);
    hgemm2(oh, ol, C_DIM, 0, wh, wl, C_DIM, 0, q, nullptr, nullptr, C_DIM, 0,
           L_Q, C_DIM, C_DIM, 1, ca_q_b, 1.f, 0);
    rms_kernel<<<L_Q, 256>>>(q, ca_nq_w);
    conv_split_kernel<<<eltBlocks, 256>>>(q, LC, qh, ql);
    conv_split_kernel<<<(int)(((long long)L_KV * C_DIM + 255) / 256), 256>>>(
        context, (long long)L_KV * C_DIM, cxh, cxl);
    trsplit(ca_k_w, C_DIM, C_DIM, wh, wl);
    hgemm2(cxh, cxl, C_DIM, 0, wh, wl, C_DIM, 0, k, nullptr, nullptr, C_DIM, 0,
           L_KV, C_DIM, C_DIM, 1, ca_k_b, 1.f, 0);
    rms_kernel<<<L_KV, 256>>>(k, ca_nk_w);
    conv_split_kernel<<<(int)(((long long)L_KV * C_DIM + 255) / 256), 256>>>(
        k, (long long)L_KV * C_DIM, kh, kl);
    trsplit(ca_v_w, C_DIM, C_DIM, wh, wl);
    hgemm2(cxh, cxl, C_DIM, 0, wh, wl, C_DIM, 0, v, nullptr, nullptr, C_DIM, 0,
           L_KV, C_DIM, C_DIM, 1, ca_v_b, 1.f, 0);
    trsplit(v, L_KV, C_DIM, vth, vtl);               // V^T [C, 512]
    hgemm2(qh, ql, C_DIM, HD, kh, kl, C_DIM, HD, s, nullptr, nullptr,
           L_KV, (long long)L_Q * L_KV, L_Q, L_KV, HD, NH, nullptr, ascale, 0);
    softmax_split_kernel<<<NH * L_Q, 256>>>(s, L_KV, ph, pl);
    hgemm2(ph, pl, L_KV, (long long)L_Q * L_KV, vth, vtl, L_KV, (long long)HD * L_KV,
           nullptr, yh, yl, C_DIM, HD, L_Q, HD, L_KV, NH, nullptr, 1.f, 0);
    trsplit(ca_o_w, C_DIM, C_DIM, wh, wl);
    hgemm2(yh, yl, C_DIM, 0, wh, wl, C_DIM, 0, t, nullptr, nullptr, C_DIM, 0,
           L_Q, C_DIM, C_DIM, 1, ca_o_b, 1.f, 0);
    add_inplace_kernel<<<eltBlocks, 256>>>(out, t);

    // ================= FFN =================
    ln_mod_split_kernel<<<L_Q, 256>>>(out, em + 3 * C_DIM, em + 4 * C_DIM, hh, hl);
    trsplit(ffn_w1, C_DIM, FF_DIM, wh, wl);          // [FF, C]
    hgemm2(hh, hl, C_DIM, 0, wh, wl, C_DIM, 0, nullptr, ffh, ffl, FF_DIM, 0,
           L_Q, FF_DIM, C_DIM, 1, ffn_b1, 1.f, 1);   // + GELU, bf16 out
    trsplit(ffn_w2, FF_DIM, C_DIM, wh, wl);          // [C, FF]
    hgemm2(ffh, ffl, FF_DIM, 0, wh, wl, FF_DIM, 0, t, nullptr, nullptr, C_DIM, 0,
           L_Q, C_DIM, FF_DIM, 1, ffn_b2, 1.f, 0);
    addmul_inplace_kernel<<<eltBlocks, 256>>>(out, t, em + 5 * C_DIM);
}